// round 7
// baseline (speedup 1.0000x reference)
#include <cuda_runtime.h>
#include <cstdint>

// Problem constants (fixed by the reference setup)
#define BATCH   4
#define HDIM    256
#define WDIM    256
#define CDIM    192
#define NHEAD   6
#define HEADD   32
#define M_TOK   (BATCH * HDIM * WDIM)   // 262144 tokens
#define NQKV    (3 * CDIM)              // 576
#define NWIN    (BATCH * (HDIM / 8) * (WDIM / 8))  // 4096 windows

// Scratch (no cudaMalloc allowed)
__device__ float g_qkv[(size_t)M_TOK * NQKV];   // 604 MB
__device__ float g_att[(size_t)M_TOK * CDIM];   // 201 MB

// ---------------------------------------------------------------------------
// Helpers
// ---------------------------------------------------------------------------
__device__ __forceinline__ uint32_t smem_u32(const void* p) {
    return (uint32_t)__cvta_generic_to_shared(p);
}

// Round-to-nearest tf32 conversion (truncation measured +0.8e-3 rel_err — keep).
__device__ __forceinline__ uint32_t f2tf32(float f) {
    uint32_t r;
    asm("cvt.rna.tf32.f32 %0, %1;" : "=r"(r) : "f"(f));
    return r;
}

__device__ __forceinline__ void mma_tf32(float* d, const uint32_t* a, const uint32_t* b) {
    asm volatile(
        "mma.sync.aligned.m16n8k8.row.col.f32.tf32.tf32.f32 "
        "{%0,%1,%2,%3}, {%4,%5,%6,%7}, {%8,%9}, {%0,%1,%2,%3};"
        : "+f"(d[0]), "+f"(d[1]), "+f"(d[2]), "+f"(d[3])
        : "r"(a[0]), "r"(a[1]), "r"(a[2]), "r"(a[3]), "r"(b[0]), "r"(b[1]));
}

// ---------------------------------------------------------------------------
// tf32 mma.sync GEMM: C[M,N] = A[M,K] @ W[N,K]^T + bias[N]
// Tile 128x96x16, 256 threads, 8 warps (4M x 2N), warp tile 32x48.
//
// SMEM holds tf32-converted bits in a fragment-major permuted layout:
//   element with local k (j=k&3, q=k>>2) of row r is at r*16 + ((j^((r>>1)&3))<<2) + q
// so ONE LDS.128 per row gives a thread k = {tig, tig+4, tig+8, tig+12}
// (both k-steps of the chunk), conflict-free for loads AND the staging stores.
// Conversion to tf32 happens once at staging -> mainloop is pure LDS.128+MMA.
// ---------------------------------------------------------------------------
#define BM 128
#define BN 96
#define BK 16
#define NCH (CDIM / BK)   // 12 chunks (K is always 192)

__global__ __launch_bounds__(256) void gemm_tc(
    const float* __restrict__ A, const float* __restrict__ W,
    const float* __restrict__ bias, float* __restrict__ C,
    int M, int N)
{
    // stage layout (uint32): A rows [0,128), B rows [128,224), 16 each
    __shared__ uint32_t sbuf[2][(BM + BN) * BK];   // 28 KB

    const int tid  = threadIdx.x;
    const int wid  = tid >> 5;
    const int lane = tid & 31;
    const int g    = lane >> 2;
    const int tig  = lane & 3;

    const int warp_m = wid & 3;    // 4 warps along M (32 rows)
    const int warp_n = wid >> 2;   // 2 warps along N (48 cols)

    const int bm = blockIdx.y * BM;
    const int bn = blockIdx.x * BN;

    const int K = CDIM;

    float acc[2][6][4];
    #pragma unroll
    for (int mt = 0; mt < 2; mt++)
        #pragma unroll
        for (int nt = 0; nt < 6; nt++)
            #pragma unroll
            for (int r = 0; r < 4; r++) acc[mt][nt][r] = 0.f;

    // ---- staging thread coordinates ----
    const int q    = tid & 3;          // which float4 along k
    const int ar0  = tid >> 2;         // A row (first), second = ar0+64
    const int ar1  = ar0 + 64;
    const int br0  = tid >> 2;         // B row 0..63
    const int br1  = 64 + (tid >> 2);  // B row 64..95 (tid < 128 only)
    const bool hasb1 = (tid < 128);
    const int aP0 = (ar0 >> 1) & 3, aP1 = (ar1 >> 1) & 3;
    const int bP0 = (br0 >> 1) & 3, bP1 = (br1 >> 1) & 3;

    const float* gA0 = A + (size_t)(bm + ar0) * K + q * 4;
    const float* gA1 = A + (size_t)(bm + ar1) * K + q * 4;
    const float* gB0 = W + (size_t)(bn + br0) * K + q * 4;
    const float* gB1 = W + (size_t)(bn + br1) * K + q * 4;

    float4 ra0, ra1, rb0, rb1;

    auto ldg_chunk = [&](int c) {
        const int k0 = c * BK;
        ra0 = *(const float4*)(gA0 + k0);
        ra1 = *(const float4*)(gA1 + k0);
        rb0 = *(const float4*)(gB0 + k0);
        if (hasb1) rb1 = *(const float4*)(gB1 + k0);
    };
    auto sts_chunk = [&](int st) {
        uint32_t* sa = sbuf[st];
        uint32_t* sb = sbuf[st] + BM * BK;
        const float* a0 = &ra0.x; const float* a1 = &ra1.x;
        const float* b0 = &rb0.x; const float* b1 = &rb1.x;
        #pragma unroll
        for (int e = 0; e < 4; e++) {
            sa[ar0 * 16 + ((e ^ aP0) << 2) + q] = f2tf32(a0[e]);
            sa[ar1 * 16 + ((e ^ aP1) << 2) + q] = f2tf32(a1[e]);
            sb[br0 * 16 + ((e ^ bP0) << 2) + q] = f2tf32(b0[e]);
        }
        if (hasb1) {
            #pragma unroll
            for (int e = 0; e < 4; e++)
                sb[br1 * 16 + ((e ^ bP1) << 2) + q] = f2tf32(b1[e]);
        }
    };

    // ---- precomputed fragment LDS offsets (uint32 index) ----
    int aoff[4], boff[6];
    #pragma unroll
    for (int i = 0; i < 4; i++) {
        int r = warp_m * 32 + i * 8 + g;
        aoff[i] = r * 16 + ((tig ^ ((r >> 1) & 3)) << 2);
    }
    #pragma unroll
    for (int j = 0; j < 6; j++) {
        int r = warp_n * 48 + j * 8 + g;
        boff[j] = BM * BK + r * 16 + ((tig ^ ((r >> 1) & 3)) << 2);
    }

    // ---- pipeline ----
    ldg_chunk(0);
    sts_chunk(0);
    __syncthreads();

    for (int c = 0; c < NCH; c++) {
        const int st = c & 1;
        if (c + 1 < NCH) ldg_chunk(c + 1);

        const uint32_t* sp = sbuf[st];
        uint4 av[4], bv[6];
        #pragma unroll
        for (int i = 0; i < 4; i++) av[i] = *(const uint4*)&sp[aoff[i]];
        #pragma unroll
        for (int j = 0; j < 6; j++) bv[j] = *(const uint4*)&sp[boff[j]];

        // k-step 0: (.x = k+tig, .y = k+tig+4)
        #pragma unroll
        for (int mt = 0; mt < 2; mt++) {
            uint32_t afr[4] = {av[2 * mt].x, av[2 * mt + 1].x,
                               av[2 * mt].y, av[2 * mt + 1].y};
            #pragma unroll
            for (int nt = 0; nt < 6; nt++) {
                uint32_t bfr[2] = {bv[nt].x, bv[nt].y};
                mma_tf32(acc[mt][nt], afr, bfr);
            }
        }
        // k-step 1: (.z = k+8+tig, .w = k+12+tig)
        #pragma unroll
        for (int mt = 0; mt < 2; mt++) {
            uint32_t afr[4] = {av[2 * mt].z, av[2 * mt + 1].z,
                               av[2 * mt].w, av[2 * mt + 1].w};
            #pragma unroll
            for (int nt = 0; nt < 6; nt++) {
                uint32_t bfr[2] = {bv[nt].z, bv[nt].w};
                mma_tf32(acc[mt][nt], afr, bfr);
            }
        }

        if (c + 1 < NCH) {
            sts_chunk(st ^ 1);
            __syncthreads();
        }
    }

    // ---- epilogue: bias + store ----
    #pragma unroll
    for (int nt = 0; nt < 6; nt++) {
        int n = bn + warp_n * 48 + nt * 8 + tig * 2;
        float2 bv2 = *(const float2*)&bias[n];
        #pragma unroll
        for (int mt = 0; mt < 2; mt++) {
            int m = bm + warp_m * 32 + mt * 16 + g;
            float2 v0 = make_float2(acc[mt][nt][0] + bv2.x, acc[mt][nt][1] + bv2.y);
            float2 v1 = make_float2(acc[mt][nt][2] + bv2.x, acc[mt][nt][3] + bv2.y);
            *(float2*)(C + (size_t)m * N + n)       = v0;
            *(float2*)(C + (size_t)(m + 8) * N + n) = v1;
        }
    }
}

// ---------------------------------------------------------------------------
// Tensor-core window attention (unchanged from R6 passing version).
// One block per window; 384 threads = 12 warps = (6 heads) x (2 M-halves).
// ---------------------------------------------------------------------------
#define HSTR 6784
#define WT_SMEM (6 * HSTR * 4)

extern __shared__ float ws[];

__global__ __launch_bounds__(384) void win_attn_tc(
    const float* __restrict__ bias,
    const float* __restrict__ qkv,
    float* __restrict__ att)
{
    const int tid  = threadIdx.x;
    const int wid  = tid >> 5;
    const int lane = tid & 31;
    const int g    = lane >> 2;
    const int tig  = lane & 3;
    const int hl   = wid >> 1;     // head 0..5
    const int mh   = wid & 1;      // M-half

    const int win = blockIdx.x;
    const int b   = win >> 10;
    const int r_  = win & 1023;
    const int wh  = r_ >> 5;
    const int ww  = r_ & 31;

    const float scale = 0.17677669529663687f;  // 1/sqrt(32)

    // ---- load q (scaled), k, vT for all 6 heads ----
    for (int idx4 = tid; idx4 < 3072; idx4 += 384) {
        int i  = idx4 / 48;        // token in window
        int c  = idx4 % 48;
        int lh = c >> 3;           // head
        int d  = (c & 7) * 4;      // dim
        int gh = wh * 8 + (i >> 3);
        int gw = ww * 8 + (i & 7);
        size_t tok = (size_t)b * (HDIM * WDIM) + (size_t)gh * WDIM + gw;
        const float* base = qkv + tok * NQKV + lh * HEADD + d;
        float4 qv = *(const float4*)base;
        float4 kv = *(const float4*)(base + CDIM);
        float4 vv = *(const float4*)(base + 2 * CDIM);
        float* hp = ws + lh * HSTR;
        qv.x *= scale; qv.y *= scale; qv.z *= scale; qv.w *= scale;
        *(float4*)&hp[i * 36 + d] = qv;
        *(float4*)&hp[2304 + i * 36 + d] = kv;
        hp[4608 + (d + 0) * 68 + i] = vv.x;
        hp[4608 + (d + 1) * 68 + i] = vv.y;
        hp[4608 + (d + 2) * 68 + i] = vv.z;
        hp[4608 + (d + 3) * 68 + i] = vv.w;
    }
    __syncthreads();

    float* hb = ws + hl * HSTR;
    const float* q_s = hb;          // [64][36]
    const float* k_s = hb + 2304;   // [64][36]
    const float* vT  = hb + 4608;   // [32][68]
    const int rbase = mh * 32;

    // ---- S = q @ k^T (32x64x32 per warp) ----
    float accS[2][8][4];
    #pragma unroll
    for (int mt = 0; mt < 2; mt++)
        #pragma unroll
        for (int nt = 0; nt < 8; nt++)
            #pragma unroll
            for (int r = 0; r < 4; r++) accS[mt][nt][r] = 0.f;

    #pragma unroll
    for (int ks = 0; ks < 4; ks++) {
        const int k0 = ks * 8;
        uint32_t afr[2][4];
        #pragma unroll
        for (int mt = 0; mt < 2; mt++) {
            int r0 = rbase + mt * 16 + g;
            afr[mt][0] = f2tf32(q_s[r0 * 36 + k0 + tig]);
            afr[mt][1] = f2tf32(q_s[(r0 + 8) * 36 + k0 + tig]);
            afr[mt][2] = f2tf32(q_s[r0 * 36 + k0 + 4 + tig]);
            afr[mt][3] = f2tf32(q_s[(r0 + 8) * 36 + k0 + 4 + tig]);
        }
        uint32_t bfr[8][2];
        #pragma unroll
        for (int nt = 0; nt < 8; nt++) {
            int n = nt * 8 + g;
            bfr[nt][0] = f2tf32(k_s[n * 36 + k0 + tig]);
            bfr[nt][1] = f2tf32(k_s[n * 36 + k0 + 4 + tig]);
        }
        #pragma unroll
        for (int mt = 0; mt < 2; mt++)
            #pragma unroll
            for (int nt = 0; nt < 8; nt++)
                mma_tf32(accS[mt][nt], afr[mt], bfr[nt]);
    }

    // ---- + bias ----
    {
        const float* bp = bias + (size_t)hl * 64 * 64;
        #pragma unroll
        for (int mt = 0; mt < 2; mt++) {
            int r0 = rbase + mt * 16 + g;
            #pragma unroll
            for (int nt = 0; nt < 8; nt++) {
                int c0 = nt * 8 + tig * 2;
                float2 b0 = *(const float2*)(bp + r0 * 64 + c0);
                float2 b1 = *(const float2*)(bp + (r0 + 8) * 64 + c0);
                accS[mt][nt][0] += b0.x;
                accS[mt][nt][1] += b0.y;
                accS[mt][nt][2] += b1.x;
                accS[mt][nt][3] += b1.y;
            }
        }
    }

    // ---- softmax (rows live in a lane quad) ----
    #pragma unroll
    for (int mt = 0; mt < 2; mt++) {
        float mx0 = -1e30f, mx1 = -1e30f;
        #pragma unroll
        for (int nt = 0; nt < 8; nt++) {
            mx0 = fmaxf(mx0, fmaxf(accS[mt][nt][0], accS[mt][nt][1]));
            mx1 = fmaxf(mx1, fmaxf(accS[mt][nt][2], accS[mt][nt][3]));
        }
        mx0 = fmaxf(mx0, __shfl_xor_sync(0xffffffffu, mx0, 1));
        mx0 = fmaxf(mx0, __shfl_xor_sync(0xffffffffu, mx0, 2));
        mx1 = fmaxf(mx1, __shfl_xor_sync(0xffffffffu, mx1, 1));
        mx1 = fmaxf(mx1, __shfl_xor_sync(0xffffffffu, mx1, 2));
        float s0 = 0.f, s1 = 0.f;
        #pragma unroll
        for (int nt = 0; nt < 8; nt++) {
            accS[mt][nt][0] = __expf(accS[mt][nt][0] - mx0);
            accS[mt][nt][1] = __expf(accS[mt][nt][1] - mx0);
            accS[mt][nt][2] = __expf(accS[mt][nt][2] - mx1);
            accS[mt][nt][3] = __expf(accS[mt][nt][3] - mx1);
            s0 += accS[mt][nt][0] + accS[mt][nt][1];
            s1 += accS[mt][nt][2] + accS[mt][nt][3];
        }
        s0 += __shfl_xor_sync(0xffffffffu, s0, 1);
        s0 += __shfl_xor_sync(0xffffffffu, s0, 2);
        s1 += __shfl_xor_sync(0xffffffffu, s1, 1);
        s1 += __shfl_xor_sync(0xffffffffu, s1, 2);
        float i0 = __frcp_rn(s0), i1 = __frcp_rn(s1);
        #pragma unroll
        for (int nt = 0; nt < 8; nt++) {
            accS[mt][nt][0] *= i0;
            accS[mt][nt][1] *= i0;
            accS[mt][nt][2] *= i1;
            accS[mt][nt][3] *= i1;
        }
    }

    // ---- pair barrier, then P overlays q+k of this head ----
    asm volatile("bar.sync %0, %1;" :: "r"(1 + hl), "r"(64) : "memory");

    float* p_s = hb;   // [64][68]
    #pragma unroll
    for (int mt = 0; mt < 2; mt++) {
        int r0 = rbase + mt * 16 + g;
        #pragma unroll
        for (int nt = 0; nt < 8; nt++) {
            int c0 = nt * 8 + tig * 2;
            *(float2*)&p_s[r0 * 68 + c0] =
                make_float2(accS[mt][nt][0], accS[mt][nt][1]);
            *(float2*)&p_s[(r0 + 8) * 68 + c0] =
                make_float2(accS[mt][nt][2], accS[mt][nt][3]);
        }
    }

    // ---- O = P @ V (32x32x64 per warp) ----
    float accO[2][4][4];
    #pragma unroll
    for (int mt = 0; mt < 2; mt++)
        #pragma unroll
        for (int nt = 0; nt < 4; nt++)
            #pragma unroll
            for (int r = 0; r < 4; r++) accO[mt][nt][r] = 0.f;

    // pair barrier: P stores must be visible to both warps of this head
    asm volatile("bar.sync %0, %1;" :: "r"(1 + hl), "r"(64) : "memory");

    #pragma unroll
    for (int ks = 0; ks < 8; ks++) {
        const int k0 = ks * 8;
        uint32_t afr[2][4];
        #pragma unroll
        for (int mt = 0; mt < 2; mt++) {
            int r0 = rbase + mt * 16 + g;
            afr[mt][0] = f2tf32(p_s[r0 * 68 + k0 + tig]);
            afr[mt][1] = f2tf32(p_s[(r0 + 8) * 68 + k0 + tig]);
            afr[mt][2] = f2tf32(p_s[r0 * 68 + k0 + 4 + tig]);
            afr[mt][3] = f2tf32(p_s[(r0 + 8) * 68 + k0 + 4 + tig]);
        }
        uint32_t bfr[4][2];
        #pragma unroll
        for (int nt = 0; nt < 4; nt++) {
            int n = nt * 8 + g;
            bfr[nt][0] = f2tf32(vT[n * 68 + k0 + tig]);
            bfr[nt][1] = f2tf32(vT[n * 68 + k0 + 4 + tig]);
        }
        #pragma unroll
        for (int mt = 0; mt < 2; mt++)
            #pragma unroll
            for (int nt = 0; nt < 4; nt++)
                mma_tf32(accO[mt][nt], afr[mt], bfr[nt]);
    }

    // ---- store O ----
    #pragma unroll
    for (int mt = 0; mt < 2; mt++) {
        int r0 = rbase + mt * 16 + g;
        #pragma unroll
        for (int half = 0; half < 2; half++) {
            int i = r0 + half * 8;
            int gh = wh * 8 + (i >> 3);
            int gw = ww * 8 + (i & 7);
            size_t tok = (size_t)b * (HDIM * WDIM) + (size_t)gh * WDIM + gw;
            float* orow = att + tok * CDIM + hl * HEADD;
            #pragma unroll
            for (int nt = 0; nt < 4; nt++) {
                int c0 = nt * 8 + tig * 2;
                *(float2*)(orow + c0) =
                    make_float2(accO[mt][nt][half * 2], accO[mt][nt][half * 2 + 1]);
            }
        }
    }
}

// ---------------------------------------------------------------------------
extern "C" void kernel_launch(void* const* d_in, const int* in_sizes, int n_in,
                              void* d_out, int out_size)
{
    const float* x      = (const float*)d_in[0];
    const float* qkv_w  = (const float*)d_in[1];
    const float* qkv_b  = (const float*)d_in[2];
    const float* proj_w = (const float*)d_in[3];
    const float* proj_b = (const float*)d_in[4];
    const float* bias   = (const float*)d_in[5];
    float* out = (float*)d_out;

    static float* qkv_ptr = nullptr;
    static float* att_ptr = nullptr;
    if (!qkv_ptr) {
        cudaGetSymbolAddress((void**)&qkv_ptr, g_qkv);
        cudaGetSymbolAddress((void**)&att_ptr, g_att);
    }
    cudaFuncSetAttribute(win_attn_tc,
                         cudaFuncAttributeMaxDynamicSharedMemorySize, WT_SMEM);

    // 1) QKV GEMM: (262144 x 576) = x @ qkv_w^T + qkv_b   (tf32 mma.sync)
    gemm_tc<<<dim3(NQKV / BN, M_TOK / BM), 256>>>(
        x, qkv_w, qkv_b, qkv_ptr, M_TOK, NQKV);

    // 2) Windowed attention (tensor cores), one block per window
    win_attn_tc<<<NWIN, 384, WT_SMEM>>>(bias, qkv_ptr, att_ptr);

    // 3) Projection GEMM: out = att @ proj_w^T + proj_b   (tf32 mma.sync)
    gemm_tc<<<dim3(CDIM / BN, M_TOK / BM), 256>>>(
        att_ptr, proj_w, proj_b, out, M_TOK, CDIM);
}

// round 9
// speedup vs baseline: 1.2002x; 1.2002x over previous
#include <cuda_runtime.h>
#include <cstdint>

// Problem constants (fixed by the reference setup)
#define BATCH   4
#define HDIM    256
#define WDIM    256
#define CDIM    192
#define NHEAD   6
#define HEADD   32
#define M_TOK   (BATCH * HDIM * WDIM)   // 262144 tokens
#define NQKV    (3 * CDIM)              // 576
#define NWIN    (BATCH * (HDIM / 8) * (WDIM / 8))  // 4096 windows

// Scratch (no cudaMalloc allowed)
__device__ float g_qkv[(size_t)M_TOK * NQKV];   // 604 MB (tf32-rounded values)
__device__ float g_att[(size_t)M_TOK * CDIM];   // 201 MB (tf32-rounded values)
__device__ float g_x  [(size_t)M_TOK * CDIM];   // 201 MB (tf32-rounded x)
__device__ float g_wq [NQKV * CDIM];            // rounded qkv_w
__device__ float g_wp [CDIM * CDIM];            // rounded proj_w

// ---------------------------------------------------------------------------
// Helpers
// ---------------------------------------------------------------------------
__device__ __forceinline__ uint32_t smem_u32(const void* p) {
    return (uint32_t)__cvta_generic_to_shared(p);
}

__device__ __forceinline__ void cp_async16(uint32_t dst, const void* src) {
    asm volatile("cp.async.cg.shared.global [%0], [%1], 16;\n" :: "r"(dst), "l"(src));
}

// Round-to-nearest tf32 (rounding is required: truncation measured +0.8e-3).
__device__ __forceinline__ uint32_t f2tf32(float f) {
    uint32_t r;
    asm("cvt.rna.tf32.f32 %0, %1;" : "=r"(r) : "f"(f));
    return r;
}
__device__ __forceinline__ float rnd_tf32(float f) {
    return __uint_as_float(f2tf32(f));
}

__device__ __forceinline__ void mma_tf32(float* d, const uint32_t* a, const uint32_t* b) {
    asm volatile(
        "mma.sync.aligned.m16n8k8.row.col.f32.tf32.tf32.f32 "
        "{%0,%1,%2,%3}, {%4,%5,%6,%7}, {%8,%9}, {%0,%1,%2,%3};"
        : "+f"(d[0]), "+f"(d[1]), "+f"(d[2]), "+f"(d[3])
        : "r"(a[0]), "r"(a[1]), "r"(a[2]), "r"(a[3]), "r"(b[0]), "r"(b[1]));
}

// ---------------------------------------------------------------------------
// Elementwise tf32 rounding pass (prologue; float4 granularity)
// ---------------------------------------------------------------------------
__global__ __launch_bounds__(256) void round_pass(
    const float4* __restrict__ in, float4* __restrict__ out, int n4)
{
    int i = blockIdx.x * blockDim.x + threadIdx.x;
    if (i < n4) {
        float4 v = in[i];
        v.x = rnd_tf32(v.x); v.y = rnd_tf32(v.y);
        v.z = rnd_tf32(v.z); v.w = rnd_tf32(v.w);
        out[i] = v;
    }
}

// ---------------------------------------------------------------------------
// tf32 mma.sync GEMM on PRE-ROUNDED operands (raw-bit fragments, no CVT):
// C[M,N] = A[M,K] @ W[N,K]^T + bias[N]   (optionally tf32-rounded on store)
// Tile 128x64x16, 256 threads, 8 warps (4M x 2N), each warp 32x32.
// Identical structure to the R6 passing version (cp.async double buffer).
// ---------------------------------------------------------------------------
#define BM 128
#define BN 64
#define BK 16

template <bool ROUND_OUT>
__global__ __launch_bounds__(256) void gemm_tc(
    const float* __restrict__ A, const float* __restrict__ W,
    const float* __restrict__ bias, float* __restrict__ C,
    int M, int N, int K)
{
    __shared__ float sA[2][BM * BK];   // 8 KB per stage
    __shared__ float sB[2][BN * BK];   // 4 KB per stage

    const int tid = threadIdx.x;
    const int wid = tid >> 5;
    const int lane = tid & 31;
    const int g   = lane >> 2;
    const int tig = lane & 3;

    const int warp_m = wid & 3;
    const int warp_n = wid >> 2;

    const int bm = blockIdx.y * BM;
    const int bn = blockIdx.x * BN;

    float acc[2][4][4];
    #pragma unroll
    for (int mt = 0; mt < 2; mt++)
        #pragma unroll
        for (int nt = 0; nt < 4; nt++)
            #pragma unroll
            for (int r = 0; r < 4; r++) acc[mt][nt][r] = 0.f;

    int mA0[2], mA1[2], cmA0[2], cmA1[2];
    #pragma unroll
    for (int mt = 0; mt < 2; mt++) {
        mA0[mt] = warp_m * 32 + mt * 16 + g;
        mA1[mt] = mA0[mt] + 8;
        cmA0[mt] = (mA0[mt] >> 1) & 3;
        cmA1[mt] = (mA1[mt] >> 1) & 3;
    }
    int nB[4], cnB[4];
    #pragma unroll
    for (int nt = 0; nt < 4; nt++) {
        nB[nt] = warp_n * 32 + nt * 8 + g;
        cnB[nt] = (nB[nt] >> 1) & 3;
    }

    const int nch = K / BK;

    auto stage = [&](int st, int c) {
        const int k0 = c * BK;
        #pragma unroll
        for (int i = 0; i < 2; i++) {
            int idx = tid + i * 256;
            int m = idx >> 2, q = idx & 3;
            int pu = m * 4 + (q ^ ((m >> 1) & 3));
            cp_async16(smem_u32(&sA[st][pu * 4]),
                       A + (size_t)(bm + m) * K + k0 + q * 4);
        }
        {
            int n = tid >> 2, q = tid & 3;
            int pu = n * 4 + (q ^ ((n >> 1) & 3));
            cp_async16(smem_u32(&sB[st][pu * 4]),
                       W + (size_t)(bn + n) * K + k0 + q * 4);
        }
        asm volatile("cp.async.commit_group;" ::: "memory");
    };

    stage(0, 0);

    for (int c = 0; c < nch; c++) {
        const int st = c & 1;
        if (c + 1 < nch) {
            stage(st ^ 1, c + 1);
            asm volatile("cp.async.wait_group 1;" ::: "memory");
        } else {
            asm volatile("cp.async.wait_group 0;" ::: "memory");
        }
        __syncthreads();

        #pragma unroll
        for (int s = 0; s < 2; s++) {
            const int q0 = 2 * s, q1 = 2 * s + 1;

            uint32_t afr[2][4];
            #pragma unroll
            for (int mt = 0; mt < 2; mt++) {
                afr[mt][0] = __float_as_uint(sA[st][mA0[mt] * 16 + (q0 ^ cmA0[mt]) * 4 + tig]);
                afr[mt][1] = __float_as_uint(sA[st][mA1[mt] * 16 + (q0 ^ cmA1[mt]) * 4 + tig]);
                afr[mt][2] = __float_as_uint(sA[st][mA0[mt] * 16 + (q1 ^ cmA0[mt]) * 4 + tig]);
                afr[mt][3] = __float_as_uint(sA[st][mA1[mt] * 16 + (q1 ^ cmA1[mt]) * 4 + tig]);
            }
            uint32_t bfr[4][2];
            #pragma unroll
            for (int nt = 0; nt < 4; nt++) {
                bfr[nt][0] = __float_as_uint(sB[st][nB[nt] * 16 + (q0 ^ cnB[nt]) * 4 + tig]);
                bfr[nt][1] = __float_as_uint(sB[st][nB[nt] * 16 + (q1 ^ cnB[nt]) * 4 + tig]);
            }
            #pragma unroll
            for (int mt = 0; mt < 2; mt++)
                #pragma unroll
                for (int nt = 0; nt < 4; nt++)
                    mma_tf32(acc[mt][nt], afr[mt], bfr[nt]);
        }
        __syncthreads();
    }

    #pragma unroll
    for (int nt = 0; nt < 4; nt++) {
        int n = bn + warp_n * 32 + nt * 8 + tig * 2;
        float2 bv = *(const float2*)&bias[n];
        #pragma unroll
        for (int mt = 0; mt < 2; mt++) {
            int m = bm + warp_m * 32 + mt * 16 + g;
            float2 v0, v1;
            if (ROUND_OUT) {
                v0 = make_float2(rnd_tf32(acc[mt][nt][0] + bv.x),
                                 rnd_tf32(acc[mt][nt][1] + bv.y));
                v1 = make_float2(rnd_tf32(acc[mt][nt][2] + bv.x),
                                 rnd_tf32(acc[mt][nt][3] + bv.y));
            } else {
                v0 = make_float2(acc[mt][nt][0] + bv.x, acc[mt][nt][1] + bv.y);
                v1 = make_float2(acc[mt][nt][2] + bv.x, acc[mt][nt][3] + bv.y);
            }
            *(float2*)(C + (size_t)m * N + n)       = v0;
            *(float2*)(C + (size_t)(m + 8) * N + n) = v1;
        }
    }
}

// ---------------------------------------------------------------------------
// Tensor-core window attention, operating on PRE-ROUNDED qkv.
// One block per window; 384 threads = 12 warps = (6 heads) x (2 M-halves).
// q/k/v fragments are raw bits (already tf32-valued); softmax scale is folded
// into the bias-add (S*scale + bias). P still cvt'd at fragment load.
// Output O stored tf32-rounded so proj's A needs no CVT.
// ---------------------------------------------------------------------------
#define HSTR 6784
#define WT_SMEM (6 * HSTR * 4)

extern __shared__ float ws[];

__global__ __launch_bounds__(384) void win_attn_tc(
    const float* __restrict__ bias,
    const float* __restrict__ qkv,
    float* __restrict__ att)
{
    const int tid  = threadIdx.x;
    const int wid  = tid >> 5;
    const int lane = tid & 31;
    const int g    = lane >> 2;
    const int tig  = lane & 3;
    const int hl   = wid >> 1;     // head 0..5
    const int mh   = wid & 1;      // M-half

    const int win = blockIdx.x;
    const int b   = win >> 10;
    const int r_  = win & 1023;
    const int wh  = r_ >> 5;
    const int ww  = r_ & 31;

    const float scale = 0.17677669529663687f;  // 1/sqrt(32)

    // ---- load q, k, vT for all 6 heads (already tf32-rounded) ----
    for (int idx4 = tid; idx4 < 3072; idx4 += 384) {
        int i  = idx4 / 48;        // token in window
        int c  = idx4 % 48;
        int lh = c >> 3;           // head
        int d  = (c & 7) * 4;      // dim
        int gh = wh * 8 + (i >> 3);
        int gw = ww * 8 + (i & 7);
        size_t tok = (size_t)b * (HDIM * WDIM) + (size_t)gh * WDIM + gw;
        const float* base = qkv + tok * NQKV + lh * HEADD + d;
        float4 qv = *(const float4*)base;
        float4 kv = *(const float4*)(base + CDIM);
        float4 vv = *(const float4*)(base + 2 * CDIM);
        float* hp = ws + lh * HSTR;
        *(float4*)&hp[i * 36 + d] = qv;
        *(float4*)&hp[2304 + i * 36 + d] = kv;
        hp[4608 + (d + 0) * 68 + i] = vv.x;
        hp[4608 + (d + 1) * 68 + i] = vv.y;
        hp[4608 + (d + 2) * 68 + i] = vv.z;
        hp[4608 + (d + 3) * 68 + i] = vv.w;
    }
    __syncthreads();

    float* hb = ws + hl * HSTR;
    const float* q_s = hb;          // [64][36]
    const float* k_s = hb + 2304;   // [64][36]
    const float* vT  = hb + 4608;   // [32][68]
    const int rbase = mh * 32;

    // ---- S = q @ k^T (32x64x32 per warp) ----
    float accS[2][8][4];
    #pragma unroll
    for (int mt = 0; mt < 2; mt++)
        #pragma unroll
        for (int nt = 0; nt < 8; nt++)
            #pragma unroll
            for (int r = 0; r < 4; r++) accS[mt][nt][r] = 0.f;

    #pragma unroll
    for (int ks = 0; ks < 4; ks++) {
        const int k0 = ks * 8;
        uint32_t afr[2][4];
        #pragma unroll
        for (int mt = 0; mt < 2; mt++) {
            int r0 = rbase + mt * 16 + g;
            afr[mt][0] = __float_as_uint(q_s[r0 * 36 + k0 + tig]);
            afr[mt][1] = __float_as_uint(q_s[(r0 + 8) * 36 + k0 + tig]);
            afr[mt][2] = __float_as_uint(q_s[r0 * 36 + k0 + 4 + tig]);
            afr[mt][3] = __float_as_uint(q_s[(r0 + 8) * 36 + k0 + 4 + tig]);
        }
        uint32_t bfr[8][2];
        #pragma unroll
        for (int nt = 0; nt < 8; nt++) {
            int n = nt * 8 + g;
            bfr[nt][0] = __float_as_uint(k_s[n * 36 + k0 + tig]);
            bfr[nt][1] = __float_as_uint(k_s[n * 36 + k0 + 4 + tig]);
        }
        #pragma unroll
        for (int mt = 0; mt < 2; mt++)
            #pragma unroll
            for (int nt = 0; nt < 8; nt++)
                mma_tf32(accS[mt][nt], afr[mt], bfr[nt]);
    }

    // ---- S*scale + bias (scale folded in; q was not pre-scaled) ----
    {
        const float* bp = bias + (size_t)hl * 64 * 64;
        #pragma unroll
        for (int mt = 0; mt < 2; mt++) {
            int r0 = rbase + mt * 16 + g;
            #pragma unroll
            for (int nt = 0; nt < 8; nt++) {
                int c0 = nt * 8 + tig * 2;
                float2 b0 = *(const float2*)(bp + r0 * 64 + c0);
                float2 b1 = *(const float2*)(bp + (r0 + 8) * 64 + c0);
                accS[mt][nt][0] = fmaf(accS[mt][nt][0], scale, b0.x);
                accS[mt][nt][1] = fmaf(accS[mt][nt][1], scale, b0.y);
                accS[mt][nt][2] = fmaf(accS[mt][nt][2], scale, b1.x);
                accS[mt][nt][3] = fmaf(accS[mt][nt][3], scale, b1.y);
            }
        }
    }

    // ---- softmax (rows live in a lane quad) ----
    #pragma unroll
    for (int mt = 0; mt < 2; mt++) {
        float mx0 = -1e30f, mx1 = -1e30f;
        #pragma unroll
        for (int nt = 0; nt < 8; nt++) {
            mx0 = fmaxf(mx0, fmaxf(accS[mt][nt][0], accS[mt][nt][1]));
            mx1 = fmaxf(mx1, fmaxf(accS[mt][nt][2], accS[mt][nt][3]));
        }
        mx0 = fmaxf(mx0, __shfl_xor_sync(0xffffffffu, mx0, 1));
        mx0 = fmaxf(mx0, __shfl_xor_sync(0xffffffffu, mx0, 2));
        mx1 = fmaxf(mx1, __shfl_xor_sync(0xffffffffu, mx1, 1));
        mx1 = fmaxf(mx1, __shfl_xor_sync(0xffffffffu, mx1, 2));
        float s0 = 0.f, s1 = 0.f;
        #pragma unroll
        for (int nt = 0; nt < 8; nt++) {
            accS[mt][nt][0] = __expf(accS[mt][nt][0] - mx0);
            accS[mt][nt][1] = __expf(accS[mt][nt][1] - mx0);
            accS[mt][nt][2] = __expf(accS[mt][nt][2] - mx1);
            accS[mt][nt][3] = __expf(accS[mt][nt][3] - mx1);
            s0 += accS[mt][nt][0] + accS[mt][nt][1];
            s1 += accS[mt][nt][2] + accS[mt][nt][3];
        }
        s0 += __shfl_xor_sync(0xffffffffu, s0, 1);
        s0 += __shfl_xor_sync(0xffffffffu, s0, 2);
        s1 += __shfl_xor_sync(0xffffffffu, s1, 1);
        s1 += __shfl_xor_sync(0xffffffffu, s1, 2);
        float i0 = __frcp_rn(s0), i1 = __frcp_rn(s1);
        #pragma unroll
        for (int nt = 0; nt < 8; nt++) {
            accS[mt][nt][0] *= i0;
            accS[mt][nt][1] *= i0;
            accS[mt][nt][2] *= i1;
            accS[mt][nt][3] *= i1;
        }
    }

    // ---- pair barrier, then P overlays q+k of this head ----
    asm volatile("bar.sync %0, %1;" :: "r"(1 + hl), "r"(64) : "memory");

    float* p_s = hb;   // [64][68]
    #pragma unroll
    for (int mt = 0; mt < 2; mt++) {
        int r0 = rbase + mt * 16 + g;
        #pragma unroll
        for (int nt = 0; nt < 8; nt++) {
            int c0 = nt * 8 + tig * 2;
            *(float2*)&p_s[r0 * 68 + c0] =
                make_float2(accS[mt][nt][0], accS[mt][nt][1]);
            *(float2*)&p_s[(r0 + 8) * 68 + c0] =
                make_float2(accS[mt][nt][2], accS[mt][nt][3]);
        }
    }

    // ---- O = P @ V (32x32x64 per warp) ----
    float accO[2][4][4];
    #pragma unroll
    for (int mt = 0; mt < 2; mt++)
        #pragma unroll
        for (int nt = 0; nt < 4; nt++)
            #pragma unroll
            for (int r = 0; r < 4; r++) accO[mt][nt][r] = 0.f;

    // pair barrier: P stores must be visible to both warps of this head
    asm volatile("bar.sync %0, %1;" :: "r"(1 + hl), "r"(64) : "memory");

    #pragma unroll
    for (int ks = 0; ks < 8; ks++) {
        const int k0 = ks * 8;
        uint32_t afr[2][4];
        #pragma unroll
        for (int mt = 0; mt < 2; mt++) {
            int r0 = rbase + mt * 16 + g;
            afr[mt][0] = f2tf32(p_s[r0 * 68 + k0 + tig]);
            afr[mt][1] = f2tf32(p_s[(r0 + 8) * 68 + k0 + tig]);
            afr[mt][2] = f2tf32(p_s[r0 * 68 + k0 + 4 + tig]);
            afr[mt][3] = f2tf32(p_s[(r0 + 8) * 68 + k0 + 4 + tig]);
        }
        uint32_t bfr[4][2];
        #pragma unroll
        for (int nt = 0; nt < 4; nt++) {
            int n = nt * 8 + g;
            bfr[nt][0] = __float_as_uint(vT[n * 68 + k0 + tig]);
            bfr[nt][1] = __float_as_uint(vT[n * 68 + k0 + 4 + tig]);
        }
        #pragma unroll
        for (int mt = 0; mt < 2; mt++)
            #pragma unroll
            for (int nt = 0; nt < 4; nt++)
                mma_tf32(accO[mt][nt], afr[mt], bfr[nt]);
    }

    // ---- store O (tf32-rounded so proj reads raw bits) ----
    #pragma unroll
    for (int mt = 0; mt < 2; mt++) {
        int r0 = rbase + mt * 16 + g;
        #pragma unroll
        for (int half = 0; half < 2; half++) {
            int i = r0 + half * 8;
            int gh = wh * 8 + (i >> 3);
            int gw = ww * 8 + (i & 7);
            size_t tok = (size_t)b * (HDIM * WDIM) + (size_t)gh * WDIM + gw;
            float* orow = att + tok * CDIM + hl * HEADD;
            #pragma unroll
            for (int nt = 0; nt < 4; nt++) {
                int c0 = nt * 8 + tig * 2;
                *(float2*)(orow + c0) =
                    make_float2(rnd_tf32(accO[mt][nt][half * 2]),
                                rnd_tf32(accO[mt][nt][half * 2 + 1]));
            }
        }
    }
}

// ---------------------------------------------------------------------------
extern "C" void kernel_launch(void* const* d_in, const int* in_sizes, int n_in,
                              void* d_out, int out_size)
{
    const float* x      = (const float*)d_in[0];
    const float* qkv_w  = (const float*)d_in[1];
    const float* qkv_b  = (const float*)d_in[2];
    const float* proj_w = (const float*)d_in[3];
    const float* proj_b = (const float*)d_in[4];
    const float* bias   = (const float*)d_in[5];
    float* out = (float*)d_out;

    static float* qkv_ptr = nullptr;
    static float* att_ptr = nullptr;
    static float* x_ptr   = nullptr;
    static float* wq_ptr  = nullptr;
    static float* wp_ptr  = nullptr;
    if (!qkv_ptr) {
        cudaGetSymbolAddress((void**)&qkv_ptr, g_qkv);
        cudaGetSymbolAddress((void**)&att_ptr, g_att);
        cudaGetSymbolAddress((void**)&x_ptr,   g_x);
        cudaGetSymbolAddress((void**)&wq_ptr,  g_wq);
        cudaGetSymbolAddress((void**)&wp_ptr,  g_wp);
    }
    cudaFuncSetAttribute(win_attn_tc,
                         cudaFuncAttributeMaxDynamicSharedMemorySize, WT_SMEM);

    // 0) Pre-round all GEMM operands to tf32 values (removes per-fragment CVT)
    {
        int n4x = (M_TOK * CDIM) / 4;
        round_pass<<<(n4x + 255) / 256, 256>>>((const float4*)x, (float4*)x_ptr, n4x);
        int n4q = (NQKV * CDIM) / 4;
        round_pass<<<(n4q + 255) / 256, 256>>>((const float4*)qkv_w, (float4*)wq_ptr, n4q);
        int n4p = (CDIM * CDIM) / 4;
        round_pass<<<(n4p + 255) / 256, 256>>>((const float4*)proj_w, (float4*)wp_ptr, n4p);
    }

    // 1) QKV GEMM (pre-rounded A/W, output rounded for attention)
    gemm_tc<true><<<dim3(NQKV / BN, M_TOK / BM), 256>>>(
        x_ptr, wq_ptr, qkv_b, qkv_ptr, M_TOK, NQKV, CDIM);

    // 2) Windowed attention (tensor cores), one block per window
    win_attn_tc<<<NWIN, 384, WT_SMEM>>>(bias, qkv_ptr, att_ptr);

    // 3) Projection GEMM (pre-rounded A/W, full-precision output)
    gemm_tc<false><<<dim3(CDIM / BN, M_TOK / BM), 256>>>(
        att_ptr, wp_ptr, proj_b, out, M_TOK, CDIM, CDIM);
}

// round 13
// speedup vs baseline: 1.2680x; 1.0565x over previous
#include <cuda_runtime.h>
#include <cstdint>

// Problem constants (fixed by the reference setup)
#define BATCH   4
#define HDIM    256
#define WDIM    256
#define CDIM    192
#define NHEAD   6
#define HEADD   32
#define M_TOK   (BATCH * HDIM * WDIM)   // 262144 tokens
#define NQKV    (3 * CDIM)              // 576
#define NWIN    (BATCH * (HDIM / 8) * (WDIM / 8))  // 4096 windows

// Scratch (no cudaMalloc allowed)
__device__ float g_qkv[(size_t)M_TOK * NQKV];   // 604 MB (tf32-rounded values)
__device__ float g_att[(size_t)M_TOK * CDIM];   // 201 MB (tf32-rounded values)
__device__ float g_wq [NQKV * CDIM];            // rounded qkv_w
__device__ float g_wp [CDIM * CDIM];            // rounded proj_w

// ---------------------------------------------------------------------------
// Helpers
// ---------------------------------------------------------------------------
__device__ __forceinline__ uint32_t smem_u32(const void* p) {
    return (uint32_t)__cvta_generic_to_shared(p);
}

__device__ __forceinline__ void cp_async16(uint32_t dst, const void* src) {
    asm volatile("cp.async.cg.shared.global [%0], [%1], 16;\n" :: "r"(dst), "l"(src));
}

// Round-to-nearest tf32 (rounding required: truncation measured +0.8e-3).
__device__ __forceinline__ uint32_t f2tf32(float f) {
    uint32_t r;
    asm("cvt.rna.tf32.f32 %0, %1;" : "=r"(r) : "f"(f));
    return r;
}
__device__ __forceinline__ float rnd_tf32(float f) {
    return __uint_as_float(f2tf32(f));
}

__device__ __forceinline__ void mma_tf32(float* d, const uint32_t* a, const uint32_t* b) {
    asm volatile(
        "mma.sync.aligned.m16n8k8.row.col.f32.tf32.tf32.f32 "
        "{%0,%1,%2,%3}, {%4,%5,%6,%7}, {%8,%9}, {%0,%1,%2,%3};"
        : "+f"(d[0]), "+f"(d[1]), "+f"(d[2]), "+f"(d[3])
        : "r"(a[0]), "r"(a[1]), "r"(a[2]), "r"(a[3]), "r"(b[0]), "r"(b[1]));
}

// ---------------------------------------------------------------------------
// Elementwise tf32 rounding pass (weights only; tiny)
// ---------------------------------------------------------------------------
__global__ __launch_bounds__(256) void round_pass(
    const float4* __restrict__ in, float4* __restrict__ out, int n4)
{
    int i = blockIdx.x * blockDim.x + threadIdx.x;
    if (i < n4) {
        float4 v = in[i];
        v.x = rnd_tf32(v.x); v.y = rnd_tf32(v.y);
        v.z = rnd_tf32(v.z); v.w = rnd_tf32(v.w);
        out[i] = v;
    }
}

// ---------------------------------------------------------------------------
// tf32 mma.sync GEMM: C[M,N] = A[M,K] @ W[N,K]^T + bias[N]
// Tile 128x64x32, 256 threads, 8 warps (4M x 2N), warp tile 32x32.
// 3-stage cp.async ring, ONE __syncthreads per K-chunk (6 chunks for K=192).
// SMEM rows are 32 floats; 16B unit q of row r lives at r*32 + ((q^(r&7))<<2):
// conflict-free for cp.async stores and all fragment LDS.
// CVT_A: apply cvt.rna.tf32 to A fragments in-loop (A not pre-rounded).
// W must be pre-rounded. ROUND_OUT: round output to tf32 values on store.
// ---------------------------------------------------------------------------
#define BM 128
#define BN 64
#define BK 32
#define NSTAGE 3
#define STG_FLOATS ((BM + BN) * BK)          // 6144 floats = 24 KB
#define GEMM_SMEM (NSTAGE * STG_FLOATS * 4)  // 72 KB

extern __shared__ float dynsm[];

template <bool CVT_A, bool ROUND_OUT>
__global__ __launch_bounds__(256) void gemm_tc(
    const float* __restrict__ A, const float* __restrict__ W,
    const float* __restrict__ bias, float* __restrict__ C,
    int M, int N, int K)
{
    const int tid  = threadIdx.x;
    const int wid  = tid >> 5;
    const int lane = tid & 31;
    const int g    = lane >> 2;
    const int tig  = lane & 3;

    const int warp_m = wid & 3;
    const int warp_n = wid >> 2;

    const int bm = blockIdx.y * BM;
    const int bn = blockIdx.x * BN;

    const uint32_t sbase = smem_u32(dynsm);

    float acc[2][4][4];
    #pragma unroll
    for (int mt = 0; mt < 2; mt++)
        #pragma unroll
        for (int nt = 0; nt < 4; nt++)
            #pragma unroll
            for (int r = 0; r < 4; r++) acc[mt][nt][r] = 0.f;

    // ---- staging coordinates (cp.async, 6 units of 16B per thread) ----
    const int srow = tid >> 3;     // 0..31
    const int sq   = tid & 7;      // 16B unit within 128B row
    const float* aSrc[4];
    uint32_t adst[4];
    #pragma unroll
    for (int i = 0; i < 4; i++) {
        int r = srow + i * 32;
        aSrc[i] = A + (size_t)(bm + r) * K + sq * 4;
        adst[i] = (uint32_t)(r * 32 + ((sq ^ (r & 7)) << 2)) * 4u;
    }
    const float* bSrc[2];
    uint32_t bdst[2];
    #pragma unroll
    for (int i = 0; i < 2; i++) {
        int r = srow + i * 32;
        bSrc[i] = W + (size_t)(bn + r) * K + sq * 4;
        bdst[i] = (uint32_t)(BM * BK + r * 32 + ((sq ^ (r & 7)) << 2)) * 4u;
    }

    auto stage = [&](int st, int c) {
        const uint32_t sb = sbase + (uint32_t)st * (STG_FLOATS * 4);
        const int k0 = c * BK;
        #pragma unroll
        for (int i = 0; i < 4; i++) cp_async16(sb + adst[i], aSrc[i] + k0);
        #pragma unroll
        for (int i = 0; i < 2; i++) cp_async16(sb + bdst[i], bSrc[i] + k0);
        asm volatile("cp.async.commit_group;" ::: "memory");
    };

    // ---- fragment load offsets (float index) ----
    int aoff[4], axor[4];
    #pragma unroll
    for (int i = 0; i < 4; i++) {
        int r = warp_m * 32 + i * 8 + g;
        aoff[i] = r * 32 + tig;
        axor[i] = r & 7;
    }
    int boff[4], bxor[4];
    #pragma unroll
    for (int j = 0; j < 4; j++) {
        int r = warp_n * 32 + j * 8 + g;
        boff[j] = BM * BK + r * 32 + tig;
        bxor[j] = r & 7;
    }

    const int NCH = K / BK;   // 6 for K=192

    stage(0, 0);
    stage(1, 1);

    for (int c = 0; c < NCH; c++) {
        if (c == NCH - 1) {
            asm volatile("cp.async.wait_group 0;" ::: "memory");
        } else {
            asm volatile("cp.async.wait_group 1;" ::: "memory");
        }
        __syncthreads();
        if (c + 2 < NCH) stage((c + 2) % NSTAGE, c + 2);

        const float* sp = dynsm + (c % NSTAGE) * STG_FLOATS;

        #pragma unroll
        for (int s = 0; s < 4; s++) {
            const int q0 = 2 * s, q1 = 2 * s + 1;

            uint32_t afr[2][4];
            #pragma unroll
            for (int mt = 0; mt < 2; mt++) {
                float a0 = sp[aoff[2 * mt]     + ((q0 ^ axor[2 * mt])     << 2)];
                float a1 = sp[aoff[2 * mt + 1] + ((q0 ^ axor[2 * mt + 1]) << 2)];
                float a2 = sp[aoff[2 * mt]     + ((q1 ^ axor[2 * mt])     << 2)];
                float a3 = sp[aoff[2 * mt + 1] + ((q1 ^ axor[2 * mt + 1]) << 2)];
                if (CVT_A) {
                    afr[mt][0] = f2tf32(a0); afr[mt][1] = f2tf32(a1);
                    afr[mt][2] = f2tf32(a2); afr[mt][3] = f2tf32(a3);
                } else {
                    afr[mt][0] = __float_as_uint(a0); afr[mt][1] = __float_as_uint(a1);
                    afr[mt][2] = __float_as_uint(a2); afr[mt][3] = __float_as_uint(a3);
                }
            }
            uint32_t bfr[4][2];
            #pragma unroll
            for (int nt = 0; nt < 4; nt++) {
                bfr[nt][0] = __float_as_uint(sp[boff[nt] + ((q0 ^ bxor[nt]) << 2)]);
                bfr[nt][1] = __float_as_uint(sp[boff[nt] + ((q1 ^ bxor[nt]) << 2)]);
            }
            #pragma unroll
            for (int mt = 0; mt < 2; mt++)
                #pragma unroll
                for (int nt = 0; nt < 4; nt++)
                    mma_tf32(acc[mt][nt], afr[mt], bfr[nt]);
        }
    }

    // ---- epilogue: bias + store ----
    #pragma unroll
    for (int nt = 0; nt < 4; nt++) {
        int n = bn + warp_n * 32 + nt * 8 + tig * 2;
        float2 bv = *(const float2*)&bias[n];
        #pragma unroll
        for (int mt = 0; mt < 2; mt++) {
            int m = bm + warp_m * 32 + mt * 16 + g;
            float2 v0, v1;
            if (ROUND_OUT) {
                v0 = make_float2(rnd_tf32(acc[mt][nt][0] + bv.x),
                                 rnd_tf32(acc[mt][nt][1] + bv.y));
                v1 = make_float2(rnd_tf32(acc[mt][nt][2] + bv.x),
                                 rnd_tf32(acc[mt][nt][3] + bv.y));
            } else {
                v0 = make_float2(acc[mt][nt][0] + bv.x, acc[mt][nt][1] + bv.y);
                v1 = make_float2(acc[mt][nt][2] + bv.x, acc[mt][nt][3] + bv.y);
            }
            *(float2*)(C + (size_t)m * N + n)       = v0;
            *(float2*)(C + (size_t)(m + 8) * N + n) = v1;
        }
    }
}

// ---------------------------------------------------------------------------
// Tensor-core window attention (unchanged from R9 passing version).
// One block per window; 384 threads = 12 warps = (6 heads) x (2 M-halves).
// ---------------------------------------------------------------------------
#define HSTR 6784
#define WT_SMEM (6 * HSTR * 4)

__global__ __launch_bounds__(384) void win_attn_tc(
    const float* __restrict__ bias,
    const float* __restrict__ qkv,
    float* __restrict__ att)
{
    float* ws = dynsm;
    const int tid  = threadIdx.x;
    const int wid  = tid >> 5;
    const int lane = tid & 31;
    const int g    = lane >> 2;
    const int tig  = lane & 3;
    const int hl   = wid >> 1;     // head 0..5
    const int mh   = wid & 1;      // M-half

    const int win = blockIdx.x;
    const int b   = win >> 10;
    const int r_  = win & 1023;
    const int wh  = r_ >> 5;
    const int ww  = r_ & 31;

    const float scale = 0.17677669529663687f;  // 1/sqrt(32)

    // ---- load q, k, vT for all 6 heads (already tf32-rounded) ----
    for (int idx4 = tid; idx4 < 3072; idx4 += 384) {
        int i  = idx4 / 48;
        int c  = idx4 % 48;
        int lh = c >> 3;
        int d  = (c & 7) * 4;
        int gh = wh * 8 + (i >> 3);
        int gw = ww * 8 + (i & 7);
        size_t tok = (size_t)b * (HDIM * WDIM) + (size_t)gh * WDIM + gw;
        const float* base = qkv + tok * NQKV + lh * HEADD + d;
        float4 qv = *(const float4*)base;
        float4 kv = *(const float4*)(base + CDIM);
        float4 vv = *(const float4*)(base + 2 * CDIM);
        float* hp = ws + lh * HSTR;
        *(float4*)&hp[i * 36 + d] = qv;
        *(float4*)&hp[2304 + i * 36 + d] = kv;
        hp[4608 + (d + 0) * 68 + i] = vv.x;
        hp[4608 + (d + 1) * 68 + i] = vv.y;
        hp[4608 + (d + 2) * 68 + i] = vv.z;
        hp[4608 + (d + 3) * 68 + i] = vv.w;
    }
    __syncthreads();

    float* hb = ws + hl * HSTR;
    const float* q_s = hb;          // [64][36]
    const float* k_s = hb + 2304;   // [64][36]
    const float* vT  = hb + 4608;   // [32][68]
    const int rbase = mh * 32;

    // ---- S = q @ k^T (32x64x32 per warp) ----
    float accS[2][8][4];
    #pragma unroll
    for (int mt = 0; mt < 2; mt++)
        #pragma unroll
        for (int nt = 0; nt < 8; nt++)
            #pragma unroll
            for (int r = 0; r < 4; r++) accS[mt][nt][r] = 0.f;

    #pragma unroll
    for (int ks = 0; ks < 4; ks++) {
        const int k0 = ks * 8;
        uint32_t afr[2][4];
        #pragma unroll
        for (int mt = 0; mt < 2; mt++) {
            int r0 = rbase + mt * 16 + g;
            afr[mt][0] = __float_as_uint(q_s[r0 * 36 + k0 + tig]);
            afr[mt][1] = __float_as_uint(q_s[(r0 + 8) * 36 + k0 + tig]);
            afr[mt][2] = __float_as_uint(q_s[r0 * 36 + k0 + 4 + tig]);
            afr[mt][3] = __float_as_uint(q_s[(r0 + 8) * 36 + k0 + 4 + tig]);
        }
        uint32_t bfr[8][2];
        #pragma unroll
        for (int nt = 0; nt < 8; nt++) {
            int n = nt * 8 + g;
            bfr[nt][0] = __float_as_uint(k_s[n * 36 + k0 + tig]);
            bfr[nt][1] = __float_as_uint(k_s[n * 36 + k0 + 4 + tig]);
        }
        #pragma unroll
        for (int mt = 0; mt < 2; mt++)
            #pragma unroll
            for (int nt = 0; nt < 8; nt++)
                mma_tf32(accS[mt][nt], afr[mt], bfr[nt]);
    }

    // ---- S*scale + bias ----
    {
        const float* bp = bias + (size_t)hl * 64 * 64;
        #pragma unroll
        for (int mt = 0; mt < 2; mt++) {
            int r0 = rbase + mt * 16 + g;
            #pragma unroll
            for (int nt = 0; nt < 8; nt++) {
                int c0 = nt * 8 + tig * 2;
                float2 b0 = *(const float2*)(bp + r0 * 64 + c0);
                float2 b1 = *(const float2*)(bp + (r0 + 8) * 64 + c0);
                accS[mt][nt][0] = fmaf(accS[mt][nt][0], scale, b0.x);
                accS[mt][nt][1] = fmaf(accS[mt][nt][1], scale, b0.y);
                accS[mt][nt][2] = fmaf(accS[mt][nt][2], scale, b1.x);
                accS[mt][nt][3] = fmaf(accS[mt][nt][3], scale, b1.y);
            }
        }
    }

    // ---- softmax (rows live in a lane quad) ----
    #pragma unroll
    for (int mt = 0; mt < 2; mt++) {
        float mx0 = -1e30f, mx1 = -1e30f;
        #pragma unroll
        for (int nt = 0; nt < 8; nt++) {
            mx0 = fmaxf(mx0, fmaxf(accS[mt][nt][0], accS[mt][nt][1]));
            mx1 = fmaxf(mx1, fmaxf(accS[mt][nt][2], accS[mt][nt][3]));
        }
        mx0 = fmaxf(mx0, __shfl_xor_sync(0xffffffffu, mx0, 1));
        mx0 = fmaxf(mx0, __shfl_xor_sync(0xffffffffu, mx0, 2));
        mx1 = fmaxf(mx1, __shfl_xor_sync(0xffffffffu, mx1, 1));
        mx1 = fmaxf(mx1, __shfl_xor_sync(0xffffffffu, mx1, 2));
        float s0 = 0.f, s1 = 0.f;
        #pragma unroll
        for (int nt = 0; nt < 8; nt++) {
            accS[mt][nt][0] = __expf(accS[mt][nt][0] - mx0);
            accS[mt][nt][1] = __expf(accS[mt][nt][1] - mx0);
            accS[mt][nt][2] = __expf(accS[mt][nt][2] - mx1);
            accS[mt][nt][3] = __expf(accS[mt][nt][3] - mx1);
            s0 += accS[mt][nt][0] + accS[mt][nt][1];
            s1 += accS[mt][nt][2] + accS[mt][nt][3];
        }
        s0 += __shfl_xor_sync(0xffffffffu, s0, 1);
        s0 += __shfl_xor_sync(0xffffffffu, s0, 2);
        s1 += __shfl_xor_sync(0xffffffffu, s1, 1);
        s1 += __shfl_xor_sync(0xffffffffu, s1, 2);
        float i0 = __frcp_rn(s0), i1 = __frcp_rn(s1);
        #pragma unroll
        for (int nt = 0; nt < 8; nt++) {
            accS[mt][nt][0] *= i0;
            accS[mt][nt][1] *= i0;
            accS[mt][nt][2] *= i1;
            accS[mt][nt][3] *= i1;
        }
    }

    // ---- pair barrier, then P overlays q+k of this head ----
    asm volatile("bar.sync %0, %1;" :: "r"(1 + hl), "r"(64) : "memory");

    float* p_s = hb;   // [64][68]
    #pragma unroll
    for (int mt = 0; mt < 2; mt++) {
        int r0 = rbase + mt * 16 + g;
        #pragma unroll
        for (int nt = 0; nt < 8; nt++) {
            int c0 = nt * 8 + tig * 2;
            *(float2*)&p_s[r0 * 68 + c0] =
                make_float2(accS[mt][nt][0], accS[mt][nt][1]);
            *(float2*)&p_s[(r0 + 8) * 68 + c0] =
                make_float2(accS[mt][nt][2], accS[mt][nt][3]);
        }
    }

    // ---- O = P @ V (32x32x64 per warp) ----
    float accO[2][4][4];
    #pragma unroll
    for (int mt = 0; mt < 2; mt++)
        #pragma unroll
        for (int nt = 0; nt < 4; nt++)
            #pragma unroll
            for (int r = 0; r < 4; r++) accO[mt][nt][r] = 0.f;

    asm volatile("bar.sync %0, %1;" :: "r"(1 + hl), "r"(64) : "memory");

    #pragma unroll
    for (int ks = 0; ks < 8; ks++) {
        const int k0 = ks * 8;
        uint32_t afr[2][4];
        #pragma unroll
        for (int mt = 0; mt < 2; mt++) {
            int r0 = rbase + mt * 16 + g;
            afr[mt][0] = f2tf32(p_s[r0 * 68 + k0 + tig]);
            afr[mt][1] = f2tf32(p_s[(r0 + 8) * 68 + k0 + tig]);
            afr[mt][2] = f2tf32(p_s[r0 * 68 + k0 + 4 + tig]);
            afr[mt][3] = f2tf32(p_s[(r0 + 8) * 68 + k0 + 4 + tig]);
        }
        uint32_t bfr[4][2];
        #pragma unroll
        for (int nt = 0; nt < 4; nt++) {
            int n = nt * 8 + g;
            bfr[nt][0] = __float_as_uint(vT[n * 68 + k0 + tig]);
            bfr[nt][1] = __float_as_uint(vT[n * 68 + k0 + 4 + tig]);
        }
        #pragma unroll
        for (int mt = 0; mt < 2; mt++)
            #pragma unroll
            for (int nt = 0; nt < 4; nt++)
                mma_tf32(accO[mt][nt], afr[mt], bfr[nt]);
    }

    // ---- store O (tf32-rounded so proj reads raw bits) ----
    #pragma unroll
    for (int mt = 0; mt < 2; mt++) {
        int r0 = rbase + mt * 16 + g;
        #pragma unroll
        for (int half = 0; half < 2; half++) {
            int i = r0 + half * 8;
            int gh = wh * 8 + (i >> 3);
            int gw = ww * 8 + (i & 7);
            size_t tok = (size_t)b * (HDIM * WDIM) + (size_t)gh * WDIM + gw;
            float* orow = att + tok * CDIM + hl * HEADD;
            #pragma unroll
            for (int nt = 0; nt < 4; nt++) {
                int c0 = nt * 8 + tig * 2;
                *(float2*)(orow + c0) =
                    make_float2(rnd_tf32(accO[mt][nt][half * 2]),
                                rnd_tf32(accO[mt][nt][half * 2 + 1]));
            }
        }
    }
}

// ---------------------------------------------------------------------------
extern "C" void kernel_launch(void* const* d_in, const int* in_sizes, int n_in,
                              void* d_out, int out_size)
{
    const float* x      = (const float*)d_in[0];
    const float* qkv_w  = (const float*)d_in[1];
    const float* qkv_b  = (const float*)d_in[2];
    const float* proj_w = (const float*)d_in[3];
    const float* proj_b = (const float*)d_in[4];
    const float* bias   = (const float*)d_in[5];
    float* out = (float*)d_out;

    static float* qkv_ptr = nullptr;
    static float* att_ptr = nullptr;
    static float* wq_ptr  = nullptr;
    static float* wp_ptr  = nullptr;
    if (!qkv_ptr) {
        cudaGetSymbolAddress((void**)&qkv_ptr, g_qkv);
        cudaGetSymbolAddress((void**)&att_ptr, g_att);
        cudaGetSymbolAddress((void**)&wq_ptr,  g_wq);
        cudaGetSymbolAddress((void**)&wp_ptr,  g_wp);
        cudaFuncSetAttribute(win_attn_tc,
                             cudaFuncAttributeMaxDynamicSharedMemorySize, WT_SMEM);
        cudaFuncSetAttribute(gemm_tc<true, true>,
                             cudaFuncAttributeMaxDynamicSharedMemorySize, GEMM_SMEM);
        cudaFuncSetAttribute(gemm_tc<false, false>,
                             cudaFuncAttributeMaxDynamicSharedMemorySize, GEMM_SMEM);
    }

    // 0) Pre-round weights to tf32 values (tiny)
    {
        int n4q = (NQKV * CDIM) / 4;
        round_pass<<<(n4q + 255) / 256, 256>>>((const float4*)qkv_w, (float4*)wq_ptr, n4q);
        int n4p = (CDIM * CDIM) / 4;
        round_pass<<<(n4p + 255) / 256, 256>>>((const float4*)proj_w, (float4*)wp_ptr, n4p);
    }

    // 1) QKV GEMM: A = raw x (CVT in-loop), W pre-rounded, output rounded
    gemm_tc<true, true><<<dim3(NQKV / BN, M_TOK / BM), 256, GEMM_SMEM>>>(
        x, wq_ptr, qkv_b, qkv_ptr, M_TOK, NQKV, CDIM);

    // 2) Windowed attention (tensor cores), one block per window
    win_attn_tc<<<NWIN, 384, WT_SMEM>>>(bias, qkv_ptr, att_ptr);

    // 3) Projection GEMM: A = att (pre-rounded by attention), full fp32 out
    gemm_tc<false, false><<<dim3(CDIM / BN, M_TOK / BM), 256, GEMM_SMEM>>>(
        att_ptr, wp_ptr, proj_b, out, M_TOK, CDIM, CDIM);
}